// round 2
// baseline (speedup 1.0000x reference)
#include <cuda_runtime.h>

#define MROWS 16384
#define R 32
#define GRAM_CTAS 64
#define GRAM_THREADS 256
#define ROWS_PER_CTA (MROWS / GRAM_CTAS)   // 256
#define TILE_ROWS 64

// Scratch (device globals: allocation-free rule)
__device__ float g_part[GRAM_CTAS][R * R * 2];   // per-CTA partial Grams
__device__ float g_U[R * R * 2];                 // R^{-1} (upper triangular, complex)
__device__ float g_Q1[MROWS * R * 2];            // intermediate Q after pass 1

// ---------------------------------------------------------------------------
// Kernel 1: partial Gram  G_cta = sum_{rows of this CTA} conj(a)^T a
// Thread t owns a 2x2 complex block of the 32x32 Gram: (2bi+di, 2bj+dj).
// ---------------------------------------------------------------------------
__global__ __launch_bounds__(GRAM_THREADS)
void gram_kernel(const float* __restrict__ Ain, int useQ1) {
    __shared__ float s[TILE_ROWS * R * 2];   // 16 KB tile: 64 rows x 32 complex
    const float* A = useQ1 ? g_Q1 : Ain;

    int t  = threadIdx.x;
    int bi = t >> 4;     // 0..15
    int bj = t & 15;     // 0..15

    float a00r = 0.f, a00i = 0.f, a01r = 0.f, a01i = 0.f;
    float a10r = 0.f, a10i = 0.f, a11r = 0.f, a11i = 0.f;

    const float* base = A + (size_t)blockIdx.x * ROWS_PER_CTA * R * 2;

    for (int tile = 0; tile < ROWS_PER_CTA / TILE_ROWS; ++tile) {
        // stage 64 rows (coalesced float4)
        const float4* src = reinterpret_cast<const float4*>(base + tile * TILE_ROWS * R * 2);
        float4* dst = reinterpret_cast<float4*>(s);
        #pragma unroll
        for (int k = 0; k < 4; ++k)
            dst[t + k * 256] = src[t + k * 256];
        __syncthreads();

        #pragma unroll 4
        for (int m = 0; m < TILE_ROWS; ++m) {
            const float* row = s + m * (R * 2);
            float4 ai = *reinterpret_cast<const float4*>(row + 4 * bi); // complex 2bi, 2bi+1
            float4 aj = *reinterpret_cast<const float4*>(row + 4 * bj); // complex 2bj, 2bj+1
            // conj(ai)*aj : re = x*u + y*v ; im = x*v - y*u
            a00r += ai.x * aj.x + ai.y * aj.y;
            a00i += ai.x * aj.y - ai.y * aj.x;
            a01r += ai.x * aj.z + ai.y * aj.w;
            a01i += ai.x * aj.w - ai.y * aj.z;
            a10r += ai.z * aj.x + ai.w * aj.y;
            a10i += ai.z * aj.y - ai.w * aj.x;
            a11r += ai.z * aj.z + ai.w * aj.w;
            a11i += ai.z * aj.w - ai.w * aj.z;
        }
        __syncthreads();
    }

    float* o = g_part[blockIdx.x];
    int i0 = 2 * bi, j0 = 2 * bj;
    o[((i0    ) * R + j0    ) * 2 + 0] = a00r;
    o[((i0    ) * R + j0    ) * 2 + 1] = a00i;
    o[((i0    ) * R + j0 + 1) * 2 + 0] = a01r;
    o[((i0    ) * R + j0 + 1) * 2 + 1] = a01i;
    o[((i0 + 1) * R + j0    ) * 2 + 0] = a10r;
    o[((i0 + 1) * R + j0    ) * 2 + 1] = a10i;
    o[((i0 + 1) * R + j0 + 1) * 2 + 0] = a11r;
    o[((i0 + 1) * R + j0 + 1) * 2 + 1] = a11i;
}

// ---------------------------------------------------------------------------
// Kernel 2: reduce partials -> G, complex Cholesky G = L L^H, W = L^{-1},
// emit U = R^{-1} = W^H  (upper triangular).
// Single CTA, 256 threads; warp 0 does the 32x32 factorization.
// L stored column-major: sL[i*64 + 2r] = L[r][i]  (conflict-free lane reads)
// W stored row-major:    sW[i*64 + 2j] = W[i][j]
// ---------------------------------------------------------------------------
__global__ __launch_bounds__(256)
void cholinv_kernel() {
    __shared__ float sG[R * R * 2];
    __shared__ float sL[R * R * 2];
    __shared__ float sW[R * R * 2];
    int t = threadIdx.x;

    // Phase A: deterministic reduction of the 64 partial Grams
    for (int e = t; e < R * R * 2; e += 256) {
        float acc = 0.f;
        #pragma unroll 8
        for (int c = 0; c < GRAM_CTAS; ++c) acc += g_part[c][e];
        sG[e] = acc;
        sL[e] = 0.f;
        sW[e] = 0.f;
    }
    __syncthreads();

    if (t < 32) {
        int r = t;
        // Phase B: Cholesky (lanes = rows)
        for (int k = 0; k < R; ++k) {
            float sre = sG[(r * R + k) * 2];
            float sim = sG[(r * R + k) * 2 + 1];
            for (int i = 0; i < k; ++i) {
                float lr_re = sL[i * 64 + 2 * r], lr_im = sL[i * 64 + 2 * r + 1];
                float lk_re = sL[i * 64 + 2 * k], lk_im = sL[i * 64 + 2 * k + 1];
                // L[r][i] * conj(L[k][i])
                sre -= lr_re * lk_re + lr_im * lk_im;
                sim -= lr_im * lk_re - lr_re * lk_im;
            }
            float d   = __shfl_sync(0xffffffffu, sre, k);
            float inv = rsqrtf(fmaxf(d, 0.f) + 1e-10f);
            if (r >= k) {
                sL[k * 64 + 2 * r]     = (r == k) ? (d * inv) : (sre * inv);
                sL[k * 64 + 2 * r + 1] = (r == k) ? 0.f : (sim * inv);
            }
            __syncwarp();
        }

        // Phase C: W = L^{-1} by forward substitution (lanes = columns j)
        int j = t;
        sW[j * 64 + 2 * j]     = 1.f / sL[j * 64 + 2 * j];
        sW[j * 64 + 2 * j + 1] = 0.f;
        __syncwarp();
        for (int r2 = 1; r2 < R; ++r2) {
            if (r2 > j) {
                float sre = 0.f, sim = 0.f;
                for (int i = j; i < r2; ++i) {
                    float l_re = sL[i * 64 + 2 * r2], l_im = sL[i * 64 + 2 * r2 + 1]; // L[r2][i]
                    float w_re = sW[i * 64 + 2 * j],  w_im = sW[i * 64 + 2 * j + 1];  // W[i][j]
                    sre += l_re * w_re - l_im * w_im;
                    sim += l_re * w_im + l_im * w_re;
                }
                float invd = 1.f / sL[r2 * 64 + 2 * r2];
                sW[r2 * 64 + 2 * j]     = -sre * invd;
                sW[r2 * 64 + 2 * j + 1] = -sim * invd;
            }
            __syncwarp();
        }
    }
    __syncthreads();

    // Phase D: U[k][j] = conj(W[j][k]) for k <= j, else 0
    for (int e = t; e < R * R; e += 256) {
        int k = e >> 5, j = e & 31;
        float ure = 0.f, uim = 0.f;
        if (k <= j) {
            ure =  sW[j * 64 + 2 * k];
            uim = -sW[j * 64 + 2 * k + 1];
        }
        g_U[2 * e]     = ure;
        g_U[2 * e + 1] = uim;
    }
}

// ---------------------------------------------------------------------------
// Kernel 3: Q = A * U  (U upper triangular, broadcast from smem).
// One row (32 complex) per thread. phase 0: A=Ain, out=g_Q1.
//                                  phase 1: A=g_Q1, out=outp (d_out).
// ---------------------------------------------------------------------------
__global__ __launch_bounds__(128)
void qmul_kernel(const float* __restrict__ Ain, float* __restrict__ outp, int phase) {
    __shared__ float sU[R * R * 2];
    int t = threadIdx.x;
    const float* A = phase ? g_Q1 : Ain;
    float* out     = phase ? outp : g_Q1;

    for (int e = t; e < R * R * 2; e += 128) sU[e] = g_U[e];
    __syncthreads();

    size_t row = (size_t)blockIdx.x * 128 + t;
    const float4* src = reinterpret_cast<const float4*>(A + row * (R * 2));

    float a[R * 2];
    #pragma unroll
    for (int k = 0; k < 16; ++k)
        reinterpret_cast<float4*>(a)[k] = src[k];

    float q[R * 2];
    #pragma unroll
    for (int j = 0; j < R * 2; ++j) q[j] = 0.f;

    for (int k = 0; k < R; ++k) {
        float are = a[2 * k], aim = a[2 * k + 1];
        for (int j = k; j < R; ++j) {
            float ure = sU[(k * R + j) * 2];
            float uim = sU[(k * R + j) * 2 + 1];
            q[2 * j]     += are * ure - aim * uim;
            q[2 * j + 1] += are * uim + aim * ure;
        }
    }

    float4* dst = reinterpret_cast<float4*>(out + row * (R * 2));
    #pragma unroll
    for (int k = 0; k < 16; ++k)
        dst[k] = reinterpret_cast<float4*>(q)[k];
}

// ---------------------------------------------------------------------------
extern "C" void kernel_launch(void* const* d_in, const int* in_sizes, int n_in,
                              void* d_out, int out_size) {
    const float* A = (const float*)d_in[0];
    float* out = (float*)d_out;

    // CholeskyQR pass 1: Q1 = A * (chol(A^H A))^{-H}
    gram_kernel<<<GRAM_CTAS, GRAM_THREADS>>>(A, 0);
    cholinv_kernel<<<1, 256>>>();
    qmul_kernel<<<MROWS / 128, 128>>>(A, out, 0);

    // CholeskyQR pass 2: Q = Q1 * (chol(Q1^H Q1))^{-H}  -> d_out
    gram_kernel<<<GRAM_CTAS, GRAM_THREADS>>>(A, 1);
    cholinv_kernel<<<1, 256>>>();
    qmul_kernel<<<MROWS / 128, 128>>>(A, out, 1);
}

// round 3
// speedup vs baseline: 1.9306x; 1.9306x over previous
#include <cuda_runtime.h>

#define MROWS 16384
#define RR 32
#define GCTAS 256
#define ROWS_PER (MROWS / GCTAS)        // 64 rows per gram CTA
#define QPAD 68                          // padded smem row stride (floats)

// Scratch (device globals: allocation-free rule)
__device__ float g_part[GCTAS][RR * RR * 2];   // per-CTA partial Grams
__device__ float g_G[RR * RR * 2];             // reduced Gram
__device__ float g_U[RR * RR * 2];             // R^{-1} (dense w/ zeros below diag)
__device__ float g_Q1[MROWS * RR * 2];         // intermediate Q after pass 1

// ---------------------------------------------------------------------------
// Kernel 1: partial Gram of A.  256 CTAs x 64 rows. Thread t owns the 2x2
// complex block (2bi.., 2bj..) of the 32x32 Gram.
// ---------------------------------------------------------------------------
__global__ __launch_bounds__(256)
void gram_kernel(const float* __restrict__ A) {
    __shared__ float s[64 * 64];   // 16 KB: 64 rows x 32 complex
    int t = threadIdx.x;

    const float4* src = reinterpret_cast<const float4*>(A + (size_t)blockIdx.x * 64 * 64);
    float4* dst = reinterpret_cast<float4*>(s);
    #pragma unroll
    for (int k = 0; k < 4; ++k)
        dst[t + k * 256] = src[t + k * 256];
    __syncthreads();

    int bi = t >> 4, bj = t & 15;
    float a00r = 0.f, a00i = 0.f, a01r = 0.f, a01i = 0.f;
    float a10r = 0.f, a10i = 0.f, a11r = 0.f, a11i = 0.f;

    #pragma unroll 8
    for (int m = 0; m < 64; ++m) {
        const float* row = s + m * 64;
        float4 ai = *reinterpret_cast<const float4*>(row + 4 * bi);
        float4 aj = *reinterpret_cast<const float4*>(row + 4 * bj);
        a00r += ai.x * aj.x + ai.y * aj.y;
        a00i += ai.x * aj.y - ai.y * aj.x;
        a01r += ai.x * aj.z + ai.y * aj.w;
        a01i += ai.x * aj.w - ai.y * aj.z;
        a10r += ai.z * aj.x + ai.w * aj.y;
        a10i += ai.z * aj.y - ai.w * aj.x;
        a11r += ai.z * aj.z + ai.w * aj.w;
        a11i += ai.z * aj.w - ai.w * aj.z;
    }

    float* o = g_part[blockIdx.x];
    int i0 = 2 * bi, j0 = 2 * bj;
    o[((i0    ) * RR + j0    ) * 2 + 0] = a00r;
    o[((i0    ) * RR + j0    ) * 2 + 1] = a00i;
    o[((i0    ) * RR + j0 + 1) * 2 + 0] = a01r;
    o[((i0    ) * RR + j0 + 1) * 2 + 1] = a01i;
    o[((i0 + 1) * RR + j0    ) * 2 + 0] = a10r;
    o[((i0 + 1) * RR + j0    ) * 2 + 1] = a10i;
    o[((i0 + 1) * RR + j0 + 1) * 2 + 0] = a11r;
    o[((i0 + 1) * RR + j0 + 1) * 2 + 1] = a11i;
}

// ---------------------------------------------------------------------------
// Kernel 2: reduce 256 partial Grams -> g_G.  16 CTAs x 128 threads,
// one thread per Gram element, coalesced across threads, MLP via 4 accs.
// ---------------------------------------------------------------------------
__global__ __launch_bounds__(128)
void reduce_kernel() {
    int idx = blockIdx.x * 128 + threadIdx.x;   // 0..2047
    float a0 = 0.f, a1 = 0.f, a2 = 0.f, a3 = 0.f;
    #pragma unroll 8
    for (int p = 0; p < GCTAS; p += 4) {
        a0 += g_part[p    ][idx];
        a1 += g_part[p + 1][idx];
        a2 += g_part[p + 2][idx];
        a3 += g_part[p + 3][idx];
    }
    g_G[idx] = (a0 + a1) + (a2 + a3);
}

// ---------------------------------------------------------------------------
// Kernel 3: complex Cholesky G = L L^H, W = L^{-1}, U = W^H (zeros below diag).
// Single CTA; warp 0 factors. L column-major (sL[i*64+2r] = L[r][i]).
// ---------------------------------------------------------------------------
__global__ __launch_bounds__(256)
void cholinv_kernel() {
    __shared__ float sG[RR * RR * 2];
    __shared__ float sL[RR * RR * 2];
    __shared__ float sW[RR * RR * 2];
    int t = threadIdx.x;

    for (int e = t; e < RR * RR * 2; e += 256) {
        sG[e] = g_G[e];
        sL[e] = 0.f;
        sW[e] = 0.f;
    }
    __syncthreads();

    if (t < 32) {
        int r = t;
        // Cholesky (lanes = rows)
        for (int k = 0; k < RR; ++k) {
            float sre = sG[(r * RR + k) * 2];
            float sim = sG[(r * RR + k) * 2 + 1];
            for (int i = 0; i < k; ++i) {
                float lr_re = sL[i * 64 + 2 * r], lr_im = sL[i * 64 + 2 * r + 1];
                float lk_re = sL[i * 64 + 2 * k], lk_im = sL[i * 64 + 2 * k + 1];
                sre -= lr_re * lk_re + lr_im * lk_im;
                sim -= lr_im * lk_re - lr_re * lk_im;
            }
            float d   = __shfl_sync(0xffffffffu, sre, k);
            float inv = rsqrtf(fmaxf(d, 0.f) + 1e-10f);
            if (r >= k) {
                sL[k * 64 + 2 * r]     = (r == k) ? (d * inv) : (sre * inv);
                sL[k * 64 + 2 * r + 1] = (r == k) ? 0.f : (sim * inv);
            }
            __syncwarp();
        }

        // W = L^{-1} forward substitution (lanes = columns j)
        int j = t;
        sW[j * 64 + 2 * j]     = 1.f / sL[j * 64 + 2 * j];
        sW[j * 64 + 2 * j + 1] = 0.f;
        __syncwarp();
        for (int r2 = 1; r2 < RR; ++r2) {
            if (r2 > j) {
                float sre = 0.f, sim = 0.f;
                for (int i = j; i < r2; ++i) {
                    float l_re = sL[i * 64 + 2 * r2], l_im = sL[i * 64 + 2 * r2 + 1];
                    float w_re = sW[i * 64 + 2 * j],  w_im = sW[i * 64 + 2 * j + 1];
                    sre += l_re * w_re - l_im * w_im;
                    sim += l_re * w_im + l_im * w_re;
                }
                float invd = 1.f / sL[r2 * 64 + 2 * r2];
                sW[r2 * 64 + 2 * j]     = -sre * invd;
                sW[r2 * 64 + 2 * j + 1] = -sim * invd;
            }
            __syncwarp();
        }
    }
    __syncthreads();

    // U[k][j] = conj(W[j][k]) for k <= j, else 0 (dense store)
    for (int e = t; e < RR * RR; e += 256) {
        int k = e >> 5, j = e & 31;
        float ure = 0.f, uim = 0.f;
        if (k <= j) {
            ure =  sW[j * 64 + 2 * k];
            uim = -sW[j * 64 + 2 * k + 1];
        }
        g_U[2 * e]     = ure;
        g_U[2 * e + 1] = uim;
    }
}

// ---------------------------------------------------------------------------
// Kernel 4: Q = src * U.  256 CTAs x 64 rows, 4 threads per row, thread g
// owns columns j = 4*jj + g.  Triangular bound is compile-time (k < 4jj+4;
// U is zero above that anyway). Output staged in padded smem -> coalesced
// float4 stores.  phase 0: src=A, dst=g_Q1, and fused gram of Q1.
// phase 1: src=g_Q1, dst=out.
// ---------------------------------------------------------------------------
__global__ __launch_bounds__(256)
void qmul_kernel(const float* __restrict__ Ain, float* __restrict__ outp, int phase) {
    __shared__ float sU[RR * RR * 2];    // 8 KB
    __shared__ float sQ[64 * QPAD];      // ~17 KB padded tile
    int t = threadIdx.x;
    const float* src = phase ? g_Q1 : Ain;
    float* out       = phase ? outp : g_Q1;

    for (int e = t; e < RR * RR * 2; e += 256) sU[e] = g_U[e];
    __syncthreads();

    int rl = t >> 2, g = t & 3;
    size_t row = (size_t)blockIdx.x * 64 + rl;
    const float4* s4 = reinterpret_cast<const float4*>(src + row * 64);

    float a[64];
    #pragma unroll
    for (int k = 0; k < 16; ++k)
        reinterpret_cast<float4*>(a)[k] = s4[k];

    #pragma unroll
    for (int jj = 0; jj < 8; ++jj) {
        int j = 4 * jj + g;
        float qre = 0.f, qim = 0.f;
        #pragma unroll
        for (int k = 0; k < 4 * jj + 4; ++k) {
            float ure = sU[(k * RR + j) * 2];
            float uim = sU[(k * RR + j) * 2 + 1];
            qre += a[2 * k] * ure - a[2 * k + 1] * uim;
            qim += a[2 * k] * uim + a[2 * k + 1] * ure;
        }
        sQ[rl * QPAD + 2 * j]     = qre;
        sQ[rl * QPAD + 2 * j + 1] = qim;
    }
    __syncthreads();

    // coalesced float4 stores: 64 rows x 16 float4
    float4* out4 = reinterpret_cast<float4*>(out + (size_t)blockIdx.x * 64 * 64);
    #pragma unroll
    for (int w = 0; w < 4; ++w) {
        int v = w * 256 + t;
        int rr = v >> 4, c4 = v & 15;
        out4[v] = *reinterpret_cast<const float4*>(sQ + rr * QPAD + c4 * 4);
    }

    if (!phase) {
        // fused gram of the Q1 tile already in smem
        int bi = t >> 4, bj = t & 15;
        float a00r = 0.f, a00i = 0.f, a01r = 0.f, a01i = 0.f;
        float a10r = 0.f, a10i = 0.f, a11r = 0.f, a11i = 0.f;

        #pragma unroll 8
        for (int m = 0; m < 64; ++m) {
            const float* rowp = sQ + m * QPAD;
            float4 ai = *reinterpret_cast<const float4*>(rowp + 4 * bi);
            float4 aj = *reinterpret_cast<const float4*>(rowp + 4 * bj);
            a00r += ai.x * aj.x + ai.y * aj.y;
            a00i += ai.x * aj.y - ai.y * aj.x;
            a01r += ai.x * aj.z + ai.y * aj.w;
            a01i += ai.x * aj.w - ai.y * aj.z;
            a10r += ai.z * aj.x + ai.w * aj.y;
            a10i += ai.z * aj.y - ai.w * aj.x;
            a11r += ai.z * aj.z + ai.w * aj.w;
            a11i += ai.z * aj.w - ai.w * aj.z;
        }

        float* o = g_part[blockIdx.x];
        int i0 = 2 * bi, j0 = 2 * bj;
        o[((i0    ) * RR + j0    ) * 2 + 0] = a00r;
        o[((i0    ) * RR + j0    ) * 2 + 1] = a00i;
        o[((i0    ) * RR + j0 + 1) * 2 + 0] = a01r;
        o[((i0    ) * RR + j0 + 1) * 2 + 1] = a01i;
        o[((i0 + 1) * RR + j0    ) * 2 + 0] = a10r;
        o[((i0 + 1) * RR + j0    ) * 2 + 1] = a10i;
        o[((i0 + 1) * RR + j0 + 1) * 2 + 0] = a11r;
        o[((i0 + 1) * RR + j0 + 1) * 2 + 1] = a11i;
    }
}

// ---------------------------------------------------------------------------
extern "C" void kernel_launch(void* const* d_in, const int* in_sizes, int n_in,
                              void* d_out, int out_size) {
    const float* A = (const float*)d_in[0];
    float* out = (float*)d_out;

    // CholeskyQR pass 1  (qmul fuses the pass-2 Gram)
    gram_kernel<<<GCTAS, 256>>>(A);
    reduce_kernel<<<16, 128>>>();
    cholinv_kernel<<<1, 256>>>();
    qmul_kernel<<<GCTAS, 256>>>(A, out, 0);

    // CholeskyQR pass 2
    reduce_kernel<<<16, 128>>>();
    cholinv_kernel<<<1, 256>>>();
    qmul_kernel<<<GCTAS, 256>>>(A, out, 1);
}

// round 4
// speedup vs baseline: 2.0489x; 1.0613x over previous
#include <cuda_runtime.h>

#define MROWS 16384
#define RR 32
#define NCTA 148
#define NTHR 256
#define TILES 256          // 64 rows each
#define QPAD 68            // padded smem row stride (floats)

// Scratch (device globals: allocation-free rule)
__device__ float g_part[NCTA][RR * RR * 2];   // per-CTA partial Grams
__device__ float g_G[RR * RR * 2];            // reduced Gram
__device__ float g_U[RR * RR * 2];            // R^{-1} (dense, zeros below diag)
__device__ float g_Q1[MROWS * RR * 2];        // intermediate Q after pass 1
__device__ unsigned g_count;                  // zero-init; monotonic arrivals
__device__ unsigned g_release;                // zero-init; monotonic barrier count

// ---------------------------------------------------------------------------
// Software grid barrier (monotonic, graph-replay safe).
// Invariant at every kernel entry/exit: g_count == NCTA * g_release.
// ---------------------------------------------------------------------------
__device__ __forceinline__ void gridbar(unsigned base_r, unsigned idx) {
    __syncthreads();
    if (threadIdx.x == 0) {
        __threadfence();
        unsigned arrived = atomicAdd(&g_count, 1u) + 1u;
        unsigned target = base_r + idx + 1u;
        if (arrived == NCTA * target)
            atomicAdd(&g_release, 1u);
        while (*(volatile unsigned*)&g_release < target)
            __nanosleep(32);
        __threadfence();
    }
    __syncthreads();
}

// ---------------------------------------------------------------------------
// Helpers operating on the shared tile (64 rows x 32 complex, stride QPAD)
// ---------------------------------------------------------------------------
struct GramAcc {
    float r00, i00, r01, i01, r10, i10, r11, i11;
    __device__ __forceinline__ void zero() {
        r00 = i00 = r01 = i01 = r10 = i10 = r11 = i11 = 0.f;
    }
    __device__ __forceinline__ void accum_tile(const float* s, int bi, int bj) {
        #pragma unroll 8
        for (int m = 0; m < 64; ++m) {
            const float* row = s + m * QPAD;
            float4 ai = *reinterpret_cast<const float4*>(row + 4 * bi);
            float4 aj = *reinterpret_cast<const float4*>(row + 4 * bj);
            r00 += ai.x * aj.x + ai.y * aj.y;
            i00 += ai.x * aj.y - ai.y * aj.x;
            r01 += ai.x * aj.z + ai.y * aj.w;
            i01 += ai.x * aj.w - ai.y * aj.z;
            r10 += ai.z * aj.x + ai.w * aj.y;
            i10 += ai.z * aj.y - ai.w * aj.x;
            r11 += ai.z * aj.z + ai.w * aj.w;
            i11 += ai.z * aj.w - ai.w * aj.z;
        }
    }
    __device__ __forceinline__ void store(float* o, int bi, int bj) {
        int i0 = 2 * bi, j0 = 2 * bj;
        o[((i0    ) * RR + j0    ) * 2 + 0] = r00;
        o[((i0    ) * RR + j0    ) * 2 + 1] = i00;
        o[((i0    ) * RR + j0 + 1) * 2 + 0] = r01;
        o[((i0    ) * RR + j0 + 1) * 2 + 1] = i01;
        o[((i0 + 1) * RR + j0    ) * 2 + 0] = r10;
        o[((i0 + 1) * RR + j0    ) * 2 + 1] = i10;
        o[((i0 + 1) * RR + j0 + 1) * 2 + 0] = r11;
        o[((i0 + 1) * RR + j0 + 1) * 2 + 1] = i11;
    }
};

// reduce 148 partials for the 16 leading CTAs
__device__ __forceinline__ void reduce_partials(int bid, int t) {
    if (bid < 16 && t < 128) {
        int e = bid * 128 + t;
        float a0 = 0.f, a1 = 0.f, a2 = 0.f, a3 = 0.f;
        #pragma unroll 4
        for (int p = 0; p < NCTA; p += 4) {
            a0 += g_part[p    ][e];
            a1 += g_part[p + 1][e];
            a2 += g_part[p + 2][e];
            a3 += g_part[p + 3][e];
        }
        g_G[e] = (a0 + a1) + (a2 + a3);
    }
}

// Cholesky + triangular inverse, executed by CTA 0 only.
// sL/sW live in the tile buffer; sG aliases sU (overwritten later by qmul).
__device__ __forceinline__ void cholinv(float* sG, float* sL, float* sW, int t) {
    for (int e = t; e < RR * RR * 2; e += NTHR) {
        sG[e] = g_G[e];
        sL[e] = 0.f;
        sW[e] = 0.f;
    }
    __syncthreads();

    if (t < 32) {
        int r = t;
        for (int k = 0; k < RR; ++k) {
            float sre = sG[(r * RR + k) * 2];
            float sim = sG[(r * RR + k) * 2 + 1];
            for (int i = 0; i < k; ++i) {
                float lr_re = sL[i * 64 + 2 * r], lr_im = sL[i * 64 + 2 * r + 1];
                float lk_re = sL[i * 64 + 2 * k], lk_im = sL[i * 64 + 2 * k + 1];
                sre -= lr_re * lk_re + lr_im * lk_im;
                sim -= lr_im * lk_re - lr_re * lk_im;
            }
            float d   = __shfl_sync(0xffffffffu, sre, k);
            float inv = rsqrtf(fmaxf(d, 0.f) + 1e-10f);
            if (r >= k) {
                sL[k * 64 + 2 * r]     = (r == k) ? (d * inv) : (sre * inv);
                sL[k * 64 + 2 * r + 1] = (r == k) ? 0.f : (sim * inv);
            }
            __syncwarp();
        }
        int j = t;
        sW[j * 64 + 2 * j]     = 1.f / sL[j * 64 + 2 * j];
        sW[j * 64 + 2 * j + 1] = 0.f;
        __syncwarp();
        for (int r2 = 1; r2 < RR; ++r2) {
            if (r2 > j) {
                float sre = 0.f, sim = 0.f;
                for (int i = j; i < r2; ++i) {
                    float l_re = sL[i * 64 + 2 * r2], l_im = sL[i * 64 + 2 * r2 + 1];
                    float w_re = sW[i * 64 + 2 * j],  w_im = sW[i * 64 + 2 * j + 1];
                    sre += l_re * w_re - l_im * w_im;
                    sim += l_re * w_im + l_im * w_re;
                }
                float invd = 1.f / sL[r2 * 64 + 2 * r2];
                sW[r2 * 64 + 2 * j]     = -sre * invd;
                sW[r2 * 64 + 2 * j + 1] = -sim * invd;
            }
            __syncwarp();
        }
    }
    __syncthreads();

    // U[k][j] = conj(W[j][k]) for k <= j, dense
    for (int e = t; e < RR * RR; e += NTHR) {
        int k = e >> 5, j = e & 31;
        float ure = 0.f, uim = 0.f;
        if (k <= j) {
            ure =  sW[j * 64 + 2 * k];
            uim = -sW[j * 64 + 2 * k + 1];
        }
        g_U[2 * e]     = ure;
        g_U[2 * e + 1] = uim;
    }
}

// ---------------------------------------------------------------------------
// The one persistent kernel.
// ---------------------------------------------------------------------------
__global__ __launch_bounds__(NTHR, 1)
void fused_cholqr2(const float* __restrict__ A, float* __restrict__ out) {
    __shared__ float sTile[64 * QPAD];   // tile / sL+sW scratch  (~17.4 KB)
    __shared__ float sU[RR * RR * 2];    // U / sG scratch        (8 KB)

    int t   = threadIdx.x;
    int bid = blockIdx.x;

    __shared__ unsigned s_base;
    if (t == 0) s_base = *(volatile unsigned*)&g_release;
    __syncthreads();
    unsigned base_r = s_base;

    int bi = t >> 4, bj = t & 15;
    int rl = t >> 2, gg = t & 3;

    // ---- Stage 1: Gram of A over my tiles ----
    {
        GramAcc acc; acc.zero();
        for (int tile = bid; tile < TILES; tile += NCTA) {
            __syncthreads();
            const float4* src = reinterpret_cast<const float4*>(A + (size_t)tile * 64 * 64);
            #pragma unroll
            for (int k = 0; k < 4; ++k) {
                int v = t + k * 256;
                int r = v >> 4, c4 = v & 15;
                *reinterpret_cast<float4*>(sTile + r * QPAD + c4 * 4) = src[v];
            }
            __syncthreads();
            acc.accum_tile(sTile, bi, bj);
        }
        acc.store(g_part[bid], bi, bj);
    }
    gridbar(base_r, 0);

    // ---- Stage 2: reduce partials -> G ----
    reduce_partials(bid, t);
    gridbar(base_r, 1);

    // ---- Stage 3: Cholesky + inverse (CTA 0) ----
    if (bid == 0) cholinv(sU, sTile, sTile + 2048, t);
    gridbar(base_r, 2);

    // ---- Stage 4: Q1 = A * U  (+ fused Gram of Q1) ----
    for (int e = t; e < RR * RR * 2; e += NTHR) sU[e] = g_U[e];
    {
        GramAcc acc; acc.zero();
        for (int tile = bid; tile < TILES; tile += NCTA) {
            __syncthreads();   // sU loaded; sTile free
            size_t row = (size_t)tile * 64 + rl;
            const float4* s4 = reinterpret_cast<const float4*>(A + row * 64);
            float a[64];
            #pragma unroll
            for (int k = 0; k < 16; ++k)
                reinterpret_cast<float4*>(a)[k] = s4[k];

            #pragma unroll
            for (int jj = 0; jj < 8; ++jj) {
                int j = 4 * jj + gg;
                float qre = 0.f, qim = 0.f;
                #pragma unroll
                for (int k = 0; k < 4 * jj + 4; ++k) {
                    float2 u = *reinterpret_cast<const float2*>(sU + (k * RR + j) * 2);
                    qre += a[2 * k] * u.x - a[2 * k + 1] * u.y;
                    qim += a[2 * k] * u.y + a[2 * k + 1] * u.x;
                }
                sTile[rl * QPAD + 2 * j]     = qre;
                sTile[rl * QPAD + 2 * j + 1] = qim;
            }
            __syncthreads();

            float4* out4 = reinterpret_cast<float4*>(g_Q1 + (size_t)tile * 64 * 64);
            #pragma unroll
            for (int w = 0; w < 4; ++w) {
                int v = w * 256 + t;
                int rr = v >> 4, c4 = v & 15;
                out4[v] = *reinterpret_cast<const float4*>(sTile + rr * QPAD + c4 * 4);
            }
            acc.accum_tile(sTile, bi, bj);
        }
        acc.store(g_part[bid], bi, bj);
    }
    gridbar(base_r, 3);

    // ---- Stage 5: reduce partials -> G ----
    reduce_partials(bid, t);
    gridbar(base_r, 4);

    // ---- Stage 6: Cholesky + inverse (CTA 0) ----
    if (bid == 0) cholinv(sU, sTile, sTile + 2048, t);
    gridbar(base_r, 5);

    // ---- Stage 7: Q = Q1 * U -> out ----
    for (int e = t; e < RR * RR * 2; e += NTHR) sU[e] = g_U[e];
    for (int tile = bid; tile < TILES; tile += NCTA) {
        __syncthreads();
        size_t row = (size_t)tile * 64 + rl;
        const float4* s4 = reinterpret_cast<const float4*>(g_Q1 + row * 64);
        float a[64];
        #pragma unroll
        for (int k = 0; k < 16; ++k)
            reinterpret_cast<float4*>(a)[k] = s4[k];

        #pragma unroll
        for (int jj = 0; jj < 8; ++jj) {
            int j = 4 * jj + gg;
            float qre = 0.f, qim = 0.f;
            #pragma unroll
            for (int k = 0; k < 4 * jj + 4; ++k) {
                float2 u = *reinterpret_cast<const float2*>(sU + (k * RR + j) * 2);
                qre += a[2 * k] * u.x - a[2 * k + 1] * u.y;
                qim += a[2 * k] * u.y + a[2 * k + 1] * u.x;
            }
            sTile[rl * QPAD + 2 * j]     = qre;
            sTile[rl * QPAD + 2 * j + 1] = qim;
        }
        __syncthreads();

        float4* out4 = reinterpret_cast<float4*>(out + (size_t)tile * 64 * 64);
        #pragma unroll
        for (int w = 0; w < 4; ++w) {
            int v = w * 256 + t;
            int rr = v >> 4, c4 = v & 15;
            out4[v] = *reinterpret_cast<const float4*>(sTile + rr * QPAD + c4 * 4);
        }
    }
}

// ---------------------------------------------------------------------------
extern "C" void kernel_launch(void* const* d_in, const int* in_sizes, int n_in,
                              void* d_out, int out_size) {
    const float* A = (const float*)d_in[0];
    float* out = (float*)d_out;
    fused_cholqr2<<<NCTA, NTHR>>>(A, out);
}